// round 8
// baseline (speedup 1.0000x reference)
#include <cuda_runtime.h>
#include <mma.h>
#include <math.h>

using namespace nvcuda;

// ---------------- problem constants ----------------
#define BB    2
#define CC    128
#define HH    512
#define WWD   512
#define HWs   (HH*WWD)
#define NWIN  4096          // 64x64 windows per batch
#define NWF   1228          // int(4096*0.3)
#define NSEL  (BB*NWF)      // 2456
#define WIN   64            // tokens per window (8x8)
#define GT    64            // global tokens (8x8 pooled)
#define XST   132           // padded smem row stride (floats)
#define SST   68            // padded stride for 64-wide score tile
#define WST   132           // weight stage row stride

// ---------------- scratch (static device memory; no allocs) ----------------
__device__ float g_score[BB*NWIN];
__device__ int   g_sel[NSEL];
__device__ int   g_cnt[BB];
__device__ float g_gx[BB*CC*GT];     // [b][c][t]
__device__ float g_k[BB*GT*CC];      // [b][t][c]
__device__ float g_v[BB*GT*CC];

// ---------------- low-level helpers ----------------
__device__ __forceinline__ void cp16(float* dst_smem, const float* src) {
    unsigned saddr = (unsigned)__cvta_generic_to_shared(dst_smem);
    asm volatile("cp.async.cg.shared.global [%0], [%1], 16;" :: "r"(saddr), "l"(src));
}
__device__ __forceinline__ void cp_commit() { asm volatile("cp.async.commit_group;"); }
template<int N> __device__ __forceinline__ void cp_wait() {
    asm volatile("cp.async.wait_group %0;" :: "n"(N));
}
__device__ __forceinline__ float gelu_exact(float x) {
    return 0.5f * x * (1.0f + erff(x * 0.70710678118654752440f));
}

typedef wmma::fragment<wmma::matrix_a, 16, 16, 8, wmma::precision::tf32, wmma::row_major> FragA;
typedef wmma::fragment<wmma::matrix_b, 16, 16, 8, wmma::precision::tf32, wmma::col_major> FragBc;
typedef wmma::fragment<wmma::matrix_b, 16, 16, 8, wmma::precision::tf32, wmma::row_major> FragBr;
typedef wmma::fragment<wmma::accumulator, 16, 16, 8, float> FragC;

__device__ __forceinline__ void cvt_a(FragA& f) {
    #pragma unroll
    for (int i = 0; i < f.num_elements; ++i) f.x[i] = wmma::__float_to_tf32(f.x[i]);
}
__device__ __forceinline__ void cvt_bc(FragBc& f) {
    #pragma unroll
    for (int i = 0; i < f.num_elements; ++i) f.x[i] = wmma::__float_to_tf32(f.x[i]);
}
__device__ __forceinline__ void cvt_br(FragBr& f) {
    #pragma unroll
    for (int i = 0; i < f.num_elements; ++i) f.x[i] = wmma::__float_to_tf32(f.x[i]);
}

// ---------------- weight stage: 64 out-channels (rows of W) into buf[64][WST] ----------------
__device__ __forceinline__ void stage_w64(const float* __restrict__ Wg, int half,
                                          float* __restrict__ buf, int tid)
{
    int row = tid >> 2;           // 0..63
    int q   = tid & 3;
    const float* src = Wg + (half * 64 + row) * CC + q * 4;
    float* dst = buf + row * WST + q * 4;
    #pragma unroll
    for (int m = 0; m < 8; ++m) cp16(dst + 16 * m, src + 16 * m);
}

// ---------------- GEMM half (wmma): Y[64][c0..c0+63] = Xs @ Wt^T ----------------
// warp -> 16 rows x 32 cols. Wt rows are local out-channels 0..63, k contiguous.
__device__ __forceinline__ void gemm_half(const float* __restrict__ Xs,
                                          const float* __restrict__ Wt,
                                          float* __restrict__ Y, int ystride,
                                          int c0, int warp)
{
    int r0 = (warp & 3) * 16;
    int cl = (warp >> 2) * 32;      // local col base within this half
    FragC acc0, acc1;
    wmma::fill_fragment(acc0, 0.0f);
    wmma::fill_fragment(acc1, 0.0f);
    #pragma unroll
    for (int k0 = 0; k0 < 128; k0 += 8) {
        FragA a;
        wmma::load_matrix_sync(a, Xs + r0 * XST + k0, XST);
        cvt_a(a);
        FragBc b0, b1;
        wmma::load_matrix_sync(b0, Wt + cl * WST + k0, WST);
        wmma::load_matrix_sync(b1, Wt + (cl + 16) * WST + k0, WST);
        cvt_bc(b0); cvt_bc(b1);
        wmma::mma_sync(acc0, a, b0, acc0);
        wmma::mma_sync(acc1, a, b1, acc1);
    }
    wmma::store_matrix_sync(Y + r0 * ystride + c0 + cl,      acc0, ystride, wmma::mem_row_major);
    wmma::store_matrix_sync(Y + r0 * ystride + c0 + cl + 16, acc1, ystride, wmma::mem_row_major);
}

// Full 64x128 GEMM; weight chunks overlapped via cp.async. Team-wide sync inside.
__device__ __forceinline__ void gemm_ws(const float* __restrict__ Xs,
                                        const float* __restrict__ Wg,
                                        float* __restrict__ Y, int ystride,
                                        float* __restrict__ Wb, int tid)
{
    stage_w64(Wg, 0, Wb, tid);              cp_commit();
    stage_w64(Wg, 1, Wb + 64 * WST, tid);   cp_commit();
    cp_wait<1>(); __syncthreads();
    gemm_half(Xs, Wb, Y, ystride, 0, tid >> 5);
    cp_wait<0>(); __syncthreads();
    gemm_half(Xs, Wb + 64 * WST, Y, ystride, 64, tid >> 5);
    __syncthreads();
}

// ---------------- S[64][64] = A @ Bs^T (K=128); scale applied in softmax ----------------
__device__ __forceinline__ void attn_scores(const float* __restrict__ A,
                                            const float* __restrict__ Bs,
                                            float* __restrict__ S, int warp)
{
    int r0 = (warp & 3) * 16;
    int cb = (warp >> 2) * 32;
    FragC acc0, acc1;
    wmma::fill_fragment(acc0, 0.0f);
    wmma::fill_fragment(acc1, 0.0f);
    #pragma unroll
    for (int k0 = 0; k0 < 128; k0 += 8) {
        FragA a;
        wmma::load_matrix_sync(a, A + r0 * XST + k0, XST);
        cvt_a(a);
        FragBc b0, b1;
        wmma::load_matrix_sync(b0, Bs + cb * XST + k0, XST);
        wmma::load_matrix_sync(b1, Bs + (cb + 16) * XST + k0, XST);
        cvt_bc(b0); cvt_bc(b1);
        wmma::mma_sync(acc0, a, b0, acc0);
        wmma::mma_sync(acc1, a, b1, acc1);
    }
    wmma::store_matrix_sync(S + r0 * SST + cb,      acc0, SST, wmma::mem_row_major);
    wmma::store_matrix_sync(S + r0 * SST + cb + 16, acc1, SST, wmma::mem_row_major);
}

// ---------------- row softmax over 64 cols (applies scale) ----------------
__device__ __forceinline__ void softmax64(float* __restrict__ S, float scale, int tid)
{
    int warp = tid >> 5, lane = tid & 31;
    for (int r = warp; r < 64; r += 8) {
        float* row = S + r * SST;
        float v0 = row[lane] * scale, v1 = row[lane + 32] * scale;
        float m = fmaxf(v0, v1);
        #pragma unroll
        for (int o = 16; o > 0; o >>= 1) m = fmaxf(m, __shfl_xor_sync(0xffffffffu, m, o));
        float e0 = __expf(v0 - m), e1 = __expf(v1 - m);
        float s  = e0 + e1;
        #pragma unroll
        for (int o = 16; o > 0; o >>= 1) s += __shfl_xor_sync(0xffffffffu, s, o);
        float inv = 1.0f / s;
        row[lane]      = e0 * inv;
        row[lane + 32] = e1 * inv;
    }
}

// ---------------- Y[64][128] (+)= S[64][64] @ V[64][128] ----------------
// warp -> 16 rows x 64 cols. ADD: preload C fragments from Y.
template <bool ADD>
__device__ __forceinline__ void av_gemm(const float* __restrict__ S,
                                        const float* __restrict__ V,
                                        float* __restrict__ Y, int warp)
{
    int r0 = (warp & 3) * 16;
    int cb = (warp >> 2) * 64;
    FragC acc[4];
    if (ADD) {
        #pragma unroll
        for (int j = 0; j < 4; ++j)
            wmma::load_matrix_sync(acc[j], Y + r0 * XST + cb + 16 * j, XST, wmma::mem_row_major);
    } else {
        #pragma unroll
        for (int j = 0; j < 4; ++j) wmma::fill_fragment(acc[j], 0.0f);
    }
    #pragma unroll
    for (int k0 = 0; k0 < 64; k0 += 8) {
        FragA a;
        wmma::load_matrix_sync(a, S + r0 * SST + k0, SST);
        cvt_a(a);
        #pragma unroll
        for (int j = 0; j < 4; ++j) {
            FragBr b;
            wmma::load_matrix_sync(b, V + k0 * XST + cb + 16 * j, XST);
            cvt_br(b);
            wmma::mma_sync(acc[j], a, b, acc[j]);
        }
    }
    #pragma unroll
    for (int j = 0; j < 4; ++j)
        wmma::store_matrix_sync(Y + r0 * XST + cb + 16 * j, acc[j], XST, wmma::mem_row_major);
}

// ---------------- kernel 1: window uncertainty scores (+ zero counters) ----------------
__global__ __launch_bounds__(256) void score_kernel(const float* __restrict__ unc)
{
    int idx = blockIdx.x * blockDim.x + threadIdx.x;
    if (idx == 0) { g_cnt[0] = 0; g_cnt[1] = 0; }
    if (idx >= BB * NWIN) return;
    int b = idx / NWIN, w = idx % NWIN;
    int wh = w >> 6, ww = w & 63;
    const float* p = unc + (size_t)b * HWs + (wh * 8) * WWD + ww * 8;
    float rs[8];
    #pragma unroll
    for (int r = 0; r < 8; ++r) {
        const float* q = p + r * WWD;
        rs[r] = ((q[0]+q[1]) + (q[2]+q[3])) + ((q[4]+q[5]) + (q[6]+q[7]));
    }
    float s = ((rs[0]+rs[1]) + (rs[2]+rs[3])) + ((rs[4]+rs[5]) + (rs[6]+rs[7]));
    g_score[idx] = s * (1.0f / 64.0f);
}

// ---------------- kernel 2: top-NWF selection by rank counting ----------------
__global__ __launch_bounds__(256) void select_kernel()
{
    __shared__ float sc[NWIN];
    int b = blockIdx.y;
    for (int i = threadIdx.x; i < NWIN; i += 256) sc[i] = g_score[b * NWIN + i];
    __syncthreads();
    int w = blockIdx.x * 256 + threadIdx.x;
    float mine = sc[w];
    int rank = 0;
    for (int j = 0; j < NWIN; ++j) {
        float v = sc[j];
        rank += (v > mine) || (v == mine && j < w);
    }
    if (rank < NWF) {
        int slot = atomicAdd(&g_cnt[b], 1);
        g_sel[b * NWF + slot] = w;
    }
}

// ---------------- kernel 3: 64x64 average pooling -> gx[b][c][t] ----------------
__global__ __launch_bounds__(256) void pool_kernel(const float* __restrict__ fm)
{
    int o  = blockIdx.x;
    int t  = o & 63;
    int bc = o >> 6;
    int p1 = t >> 3, p2 = t & 7;
    const float* base = fm + (size_t)bc * HWs + p1 * 64 * WWD + p2 * 64;
    int row  = threadIdx.x >> 2;
    int cseg = threadIdx.x & 3;
    const float* q = base + row * WWD + cseg * 16;
    float s = 0.f;
    #pragma unroll
    for (int i = 0; i < 16; ++i) s += q[i];
    __shared__ float red[256];
    red[threadIdx.x] = s;
    __syncthreads();
    for (int st = 128; st > 0; st >>= 1) {
        if (threadIdx.x < st) red[threadIdx.x] += red[threadIdx.x + st];
        __syncthreads();
    }
    if (threadIdx.x == 0) g_gx[o] = red[0] * (1.0f / 4096.0f);
}

// ---------------- kernel 4: global k,v = g @ kv_g_w.T ----------------
__global__ __launch_bounds__(256) void kv_kernel(const float* __restrict__ kvw)
{
    __shared__ float gs[GT * XST];
    int b = blockIdx.y, chunk = blockIdx.x;
    int tid = threadIdx.x;
    for (int i = tid; i < GT * CC; i += 256) {
        int t = i & 63, c = i >> 6;
        gs[t * XST + c] = g_gx[(b * CC + c) * GT + t];
    }
    __syncthreads();
    int t = tid & 63;
    int qg = tid >> 6;
    float acc[8] = {0,0,0,0,0,0,0,0};
    const float4* xr = (const float4*)(gs + t * XST);
    for (int k4 = 0; k4 < 32; ++k4) {
        float4 x = xr[k4];
        #pragma unroll
        for (int j = 0; j < 8; ++j) {
            int oc = chunk * 32 + qg * 8 + j;
            float4 wv = __ldg(((const float4*)(kvw + oc * CC)) + k4);
            acc[j] += x.x*wv.x + x.y*wv.y + x.z*wv.z + x.w*wv.w;
        }
    }
    #pragma unroll
    for (int j = 0; j < 8; ++j) {
        int oc = chunk * 32 + qg * 8 + j;
        if (oc < CC) g_k[(b * GT + t) * CC + oc]      = acc[j];
        else         g_v[(b * GT + t) * CC + oc - CC] = acc[j];
    }
}

// ---------------- kernel 5: fully fused per-window pipeline (tf32 tensor cores) ----------------
__global__ __launch_bounds__(256, 1) void fused_kernel(
    const float* __restrict__ fm, float* __restrict__ out,
    const float* __restrict__ Wq,
    const float* __restrict__ W0, const float* __restrict__ b0,
    const float* __restrict__ Wqkv,
    const float* __restrict__ Wp, const float* __restrict__ bp)
{
    extern __shared__ float sm[];
    float* Xs = sm;                          // wf tile      [64][XST]
    float* A  = sm + 1 * 64 * XST;           // q / scratch  [64][XST]
    float* Bk = sm + 2 * 64 * XST;           // k tile       [64][XST]
    float* Cv = sm + 3 * 64 * XST;           // v tile       [64][XST]
    float* S  = sm + 4 * 64 * XST;           // scores       [64][SST]
    float* Wb = S + 64 * SST;                // weight chunks [2][64][WST]

    int s    = blockIdx.x;
    int b    = s / NWF;
    int w    = g_sel[s];
    int wh   = w >> 6, ww = w & 63;
    int tid  = threadIdx.x;
    int warp = tid >> 5;
    const float scale = 0.08838834764831845f;   // 128^-0.5

    // P1: gather window + load global k,v
    for (int i = tid; i < WIN * CC; i += 256) {
        int c = i >> 6, t = i & 63;
        int tr = t >> 3, tc2 = t & 7;
        Xs[t * XST + c] = fm[(size_t)(b * CC + c) * HWs + (wh * 8 + tr) * WWD + (ww * 8 + tc2)];
    }
    for (int i = tid; i < GT * CC; i += 256) {
        int t = i >> 7, c = i & 127;
        Bk[t * XST + c] = g_k[b * GT * CC + i];
        Cv[t * XST + c] = g_v[b * GT * CC + i];
    }
    __syncthreads();

    // P2: q = wf @ Wq^T
    gemm_ws(Xs, Wq, A, XST, Wb, tid);

    // P3-P5: cross attention vs 64 global tokens; wf += attn @ v
    attn_scores(A, Bk, S, warp);
    __syncthreads();
    softmax64(S, scale, tid);
    __syncthreads();
    av_gemm<true>(S, Cv, Xs, warp);
    __syncthreads();

    // P6: wf += gelu(wf @ W0^T + b0)
    gemm_ws(Xs, W0, A, XST, Wb, tid);
    for (int i = tid; i < WIN * CC; i += 256) {
        int t = i >> 7, c = i & 127;
        Xs[t * XST + c] += gelu_exact(A[t * XST + c] + __ldg(b0 + c));
    }
    __syncthreads();

    // P7: qkv projections
    gemm_ws(Xs, Wqkv,            A,  XST, Wb, tid);
    gemm_ws(Xs, Wqkv + 1*CC*CC,  Bk, XST, Wb, tid);
    gemm_ws(Xs, Wqkv + 2*CC*CC,  Cv, XST, Wb, tid);

    // P8: window self-attention
    attn_scores(A, Bk, S, warp);
    __syncthreads();
    softmax64(S, scale, tid);
    __syncthreads();
    av_gemm<false>(S, Cv, A, warp);     // A = attn @ v   [q][c]
    __syncthreads();

    // P9: wf[i][j] += av[j%64][2*i + j/64]   (swapaxes(1,2).reshape)
    for (int i = tid; i < WIN * CC; i += 256) {
        int t = i >> 7, c = i & 127;
        Xs[t * XST + c] += A[(c & 63) * XST + (2 * t + (c >> 6))];
    }
    __syncthreads();

    // P10: wf += gelu(wf @ Wp^T + bp)
    gemm_ws(Xs, Wp, A, XST, Wb, tid);
    for (int i = tid; i < WIN * CC; i += 256) {
        int t = i >> 7, c = i & 127;
        Xs[t * XST + c] += gelu_exact(A[t * XST + c] + __ldg(bp + c));
    }
    __syncthreads();

    // P11: scatter back into output
    for (int i = tid; i < WIN * CC; i += 256) {
        int c = i >> 6, t = i & 63;
        int tr = t >> 3, tc2 = t & 7;
        out[(size_t)(b * CC + c) * HWs + (wh * 8 + tr) * WWD + (ww * 8 + tc2)] = Xs[t * XST + c];
    }
}

// ---------------- launch ----------------
extern "C" void kernel_launch(void* const* d_in, const int* in_sizes, int n_in,
                              void* d_out, int out_size)
{
    const float* fm    = (const float*)d_in[0];
    const float* unc   = (const float*)d_in[1];
    const float* q_g_w = (const float*)d_in[2];
    const float* kv_w  = (const float*)d_in[3];
    const float* w0    = (const float*)d_in[4];
    const float* b0    = (const float*)d_in[5];
    const float* wqkv  = (const float*)d_in[6];
    const float* wp    = (const float*)d_in[7];
    const float* bp    = (const float*)d_in[8];
    float* out = (float*)d_out;

    const int FUSED_SMEM = (4 * 64 * XST + 64 * SST + 2 * 64 * WST) * (int)sizeof(float); // ~215 KB
    cudaFuncSetAttribute(fused_kernel, cudaFuncAttributeMaxDynamicSharedMemorySize, FUSED_SMEM);

    // out = feature_map (untouched windows), selected windows overwritten by fused_kernel
    cudaMemcpyAsync(out, fm, sizeof(float) * (size_t)BB * CC * HH * WWD,
                    cudaMemcpyDeviceToDevice);

    score_kernel<<<(BB * NWIN + 255) / 256, 256>>>(unc);
    select_kernel<<<dim3(16, BB), 256>>>();
    pool_kernel<<<BB * CC * GT, 256>>>(fm);
    kv_kernel<<<dim3(8, BB), 256>>>(kv_w);
    fused_kernel<<<NSEL, 256, FUSED_SMEM>>>(fm, out, q_g_w, w0, b0, wqkv, wp, bp);
}